// round 9
// baseline (speedup 1.0000x reference)
#include <cuda_runtime.h>
#include <cuda_bf16.h>
#include <cstdint>
#include <cstddef>

typedef unsigned long long u64;
typedef unsigned int u32;
typedef unsigned short u16;

// ---------------------------------------------------------------------------
// Scratch buffers (device globals; no allocations anywhere).
// B1..B6 hold packed bf16(hi,lo) u32 per element; B7 holds fp32.
// ---------------------------------------------------------------------------
static constexpr size_t S_B1 = 64ull * 96 * 4092;
static constexpr size_t S_B2 = 64ull * 96 * 2044;
static constexpr size_t S_B3 = 64ull * 96 * 1020;
static constexpr size_t S_B4 = 64ull * 96 * 508;
static constexpr size_t S_B5 = 64ull * 96 * 125;
static constexpr size_t S_B6 = 64ull * 96 * 29;
static constexpr size_t S_B7 = 64ull * 128 * 14;

static constexpr size_t OFF_B1 = 0;
static constexpr size_t OFF_B2 = OFF_B1 + S_B1;
static constexpr size_t OFF_B3 = OFF_B2 + S_B2;
static constexpr size_t OFF_B4 = OFF_B3 + S_B3;
static constexpr size_t OFF_B5 = OFF_B4 + S_B4;
static constexpr size_t OFF_B6 = OFF_B5 + S_B5;
static constexpr size_t OFF_B7 = OFF_B6 + S_B6;
static constexpr size_t SCRATCH_TOTAL = OFF_B7 + S_B7;

__device__ u32 g_scratch[SCRATCH_TOTAL];

// pre-split weights (bf16 hi/lo), layout [NCH][O][64] with chunk = CPC
// channels x K taps (c = li*K + k), zero-padded.
static constexpr int W1H = 0,      W1L = 43008;    // O=96  NCH=7 (CPC=6, K=10)
static constexpr int W2H = 86016,  W2L = 135168;   // O=96  NCH=8 (CPC=12, K=5)
static constexpr int W3H = 184320, W3L = 233472;
static constexpr int W4H = 282624, W4L = 331776;
static constexpr int W5H = 380928, W5L = 430080;
static constexpr int W6H = 479232, W6L = 528384;
static constexpr int W7H = 577536, W7L = 618496;   // O=128 NCH=5 (CPC=21, K=3)
__device__ __align__(256) u16 g_wsplit[659456];

// ---------------------------------------------------------------------------
// PTX helpers (baseline ISA only — compiles at compute_103)
// ---------------------------------------------------------------------------
__device__ __forceinline__ void ldsm_x4(u32* r, u32 addr) {
    asm volatile("ldmatrix.sync.aligned.m8n8.x4.shared.b16 {%0,%1,%2,%3}, [%4];"
                 : "=r"(r[0]), "=r"(r[1]), "=r"(r[2]), "=r"(r[3]) : "r"(addr));
}
__device__ __forceinline__ void mma_bf16(float* d, const u32* a, const u32* b) {
    asm volatile(
        "mma.sync.aligned.m16n8k16.row.col.f32.bf16.bf16.f32 "
        "{%0,%1,%2,%3}, {%4,%5,%6,%7}, {%8,%9}, {%0,%1,%2,%3};"
        : "+f"(d[0]), "+f"(d[1]), "+f"(d[2]), "+f"(d[3])
        : "r"(a[0]), "r"(a[1]), "r"(a[2]), "r"(a[3]), "r"(b[0]), "r"(b[1]));
}
#define CP_ASYNC16(dst, src) \
    asm volatile("cp.async.cg.shared.global [%0], [%1], 16;" \
                 :: "r"((u32)(dst)), "l"(src) : "memory")
#define CP_ASYNC_COMMIT() asm volatile("cp.async.commit_group;" ::: "memory")
#define CP_ASYNC_WAIT0()  asm volatile("cp.async.wait_group 0;" ::: "memory")
#define STS128(addr, a, b, c, d) \
    asm volatile("st.shared.v4.b32 [%0], {%1, %2, %3, %4};" \
                 :: "r"((u32)(addr)), "r"(a), "r"(b), "r"(c), "r"(d) : "memory")

__device__ __forceinline__ u32 smem_u32(const void* p) {
    u32 a;
    asm("{ .reg .u64 t; cvta.to.shared.u64 t, %1; cvt.u32.u64 %0, t; }"
        : "=r"(a) : "l"(p));
    return a;
}

// fp32 -> packed (bf16 hi | bf16 lo << 16), value ~= hi + lo
__device__ __forceinline__ u32 split1(float v) {
    __nv_bfloat16 h = __float2bfloat16_rn(v);
    __nv_bfloat16 l = __float2bfloat16_rn(v - __bfloat162float(h));
    return (u32)__bfloat16_as_ushort(h) | ((u32)__bfloat16_as_ushort(l) << 16);
}
__device__ __forceinline__ float unsplit1(u32 p) {
    return __bfloat162float(__ushort_as_bfloat16((u16)(p & 0xFFFF))) +
           __bfloat162float(__ushort_as_bfloat16((u16)(p >> 16)));
}

// layout constants (host + device agree)
__host__ __device__ constexpr int cx_cpc(int K)   { return 64 / K; }
__host__ __device__ constexpr int cx_uspan(int K) { return 128 + K; }
__host__ __device__ constexpr int cx_xp(int K)    { return (cx_uspan(K) + 3) & ~3; }
__host__ __device__ constexpr int cx_xsb(int K) {           // one xsp buf bytes
    return (cx_cpc(K) + 1) * cx_xp(K) * 4;                   // +1 zero pad row
}
__host__ __device__ constexpr int cx_aoff(int K) {
    return (512 + 2 * cx_xsb(K) + 15) & ~15;
}
__host__ __device__ constexpr int cx_boff(int K) {
    return cx_aoff(K) + 4 * 64 * 144;
}
__host__ __device__ constexpr int cx_smem(int K, int O) {
    int total = cx_boff(K) + 4 * O * 144;
    int dmin = 512 + 64 * (O + 1) * 4;
    return total > dmin ? total : dmin;
}

// ---------------------------------------------------------------------------
// Weight pre-split into chunked layout [NCH][O][64], c = li*K + k
// ---------------------------------------------------------------------------
__global__ void presplit_w_kernel(
    const float* __restrict__ w1, const float* __restrict__ w2,
    const float* __restrict__ w3, const float* __restrict__ w4,
    const float* __restrict__ w5, const float* __restrict__ w6,
    const float* __restrict__ w7) {
    int n = blockIdx.x * blockDim.x + threadIdx.x;
    const float* w; int I, O, K; u16 *hi, *lo; int idx;
    if      (n < 43008)  { w = w1; I = 40; O = 96;  K = 10; hi = g_wsplit + W1H; lo = g_wsplit + W1L; idx = n; }
    else if (n < 92160)  { w = w2; I = 96; O = 96;  K = 5;  hi = g_wsplit + W2H; lo = g_wsplit + W2L; idx = n - 43008; }
    else if (n < 141312) { w = w3; I = 96; O = 96;  K = 5;  hi = g_wsplit + W3H; lo = g_wsplit + W3L; idx = n - 92160; }
    else if (n < 190464) { w = w4; I = 96; O = 96;  K = 5;  hi = g_wsplit + W4H; lo = g_wsplit + W4L; idx = n - 141312; }
    else if (n < 239616) { w = w5; I = 96; O = 96;  K = 5;  hi = g_wsplit + W5H; lo = g_wsplit + W5L; idx = n - 190464; }
    else if (n < 288768) { w = w6; I = 96; O = 96;  K = 5;  hi = g_wsplit + W6H; lo = g_wsplit + W6L; idx = n - 239616; }
    else if (n < 329728) { w = w7; I = 96; O = 128; K = 3;  hi = g_wsplit + W7H; lo = g_wsplit + W7L; idx = n - 288768; }
    else return;
    int CPC = 64 / K;
    int c  = idx & 63;
    int o  = (idx >> 6) % O;
    int ch = idx / (64 * O);
    int li = c / K;
    int k  = c - li * K;
    int i  = ch * CPC + li;
    float v = (li < CPC && i < I) ? w[(o * I + i) * K + k] : 0.f;
    u32 p = split1(v);
    hi[idx] = (u16)(p & 0xFFFF);
    lo[idx] = (u16)(p >> 16);
}

// ---------------------------------------------------------------------------
// Implicit-GEMM conv via HMMA, bf16 split, 3 passes, software-pipelined:
// double-buffered x-slice / A-tile / B-tile, one barrier per chunk, staging
// of chunk ch+1 overlapped with compute of chunk ch. M tile = 64; 8 warps =
// 4 m-warps x 2 n-warps; warp tile m16 x n(O/2). 2 CTAs/SM (conv7: 1).
// IN_MODE: 0 = fp32 input, 1 = packed u32 input, 2 = packed + avgpool2 + relu
// ---------------------------------------------------------------------------
template <int I, int O, int K, bool RELU, int IN_MODE, bool OUT_PACKED>
__global__ __launch_bounds__(256, 2)
void conv_hmma_kernel(const void* __restrict__ xv,
                      const u16* __restrict__ whi, const u16* __restrict__ wlo,
                      const float* __restrict__ bias, void* __restrict__ yv,
                      int Tin, int TinRaw, int Tconv) {
    constexpr int CPC   = cx_cpc(K);
    constexpr int NCH   = (I + CPC - 1) / CPC;
    constexpr int USPAN = cx_uspan(K);
    constexpr int XP    = cx_xp(K);
    constexpr int XROWS = CPC + 1;           // +1 zero pad row
    constexpr int A_OFF = cx_aoff(K);
    constexpr int B_OFF = cx_boff(K);
    constexpr int APB   = 64 * 144;          // one A tile bytes
    constexpr int BPB   = O * 144;           // one B tile bytes
    constexpr int NP    = O / 32;            // n-tile pairs per warp
    constexpr int DP    = O + 1;

    extern __shared__ char smem[];
    const u32 sm = smem_u32(smem);
    float* bias_sh = reinterpret_cast<float*>(smem);
    u32*   xsp     = reinterpret_cast<u32*>(smem + 512);   // [2][XROWS][XP]

    const int b    = blockIdx.y;
    const int t0   = blockIdx.x * 64;
    const int tid  = threadIdx.x;
    const int wid  = tid >> 5;
    const int lane = tid & 31;
    const int mw   = wid & 3;
    const int nw   = wid >> 2;
    const int tA   = tid >> 3;               // gather: time row
    const int gA   = tid & 7;                // gather: 8-col group

    if (tid < O) bias_sh[tid] = bias[tid];
    // zero the pad row (row CPC) of both xsp buffers (never rewritten)
    if (tid < XP) {
        xsp[0 * XROWS * XP + CPC * XP + tid] = 0;
        xsp[1 * XROWS * XP + CPC * XP + tid] = 0;
    }

    // chunk-invariant gather offsets: col cg = gA*8+e -> (li, k)
    int goff[8];
#pragma unroll
    for (int e = 0; e < 8; e++) {
        int cg = gA * 8 + e;
        int li = cg / K;                      // li == CPC lands on pad row
        int k  = cg - li * K;
        goff[e] = li * XP + k;
    }

    // ldsm lane offsets
    const u32 a_loff = (u32)((16 * mw + (lane & 7) + ((lane >> 3) & 1) * 8) * 144
                             + (lane >> 4) * 16);
    const u32 b_loff = (u32)((nw * (O / 2) + ((lane >> 4) << 3) + (lane & 7)) * 144
                             + ((lane >> 3) & 1) * 16);

    float acc[2 * NP][4];
#pragma unroll
    for (int nt = 0; nt < 2 * NP; nt++)
#pragma unroll
        for (int q = 0; q < 4; q++) acc[nt][q] = 0.f;

    // ---- staging helpers (inlined lambdas) ---------------------------------
    auto stage_x = [&](int buf, int ch) {
        u32* xb = xsp + buf * XROWS * XP;
        for (int n = tid; n < CPC * USPAN; n += 256) {
            int li = n / USPAN;
            int u  = n - li * USPAN;
            int i  = ch * CPC + li;
            int tg = 2 * t0 + u;
            u32 pv = 0;
            if (i < I && tg < Tin) {
                if (IN_MODE == 0) {
                    const float* xf = (const float*)xv;
                    pv = split1(xf[((size_t)b * I + i) * Tin + tg]);
                } else if (IN_MODE == 1) {
                    const u32* xu = (const u32*)xv;
                    pv = xu[((size_t)b * I + i) * Tin + tg];
                } else {
                    const u32* xu = (const u32*)xv;
                    const u32* row = xu + ((size_t)b * I + i) * TinRaw + 2 * tg;
                    float f = 0.5f * (unsplit1(row[0]) + unsplit1(row[1]));
                    pv = split1(fmaxf(f, 0.f));
                }
            }
            xb[li * XP + u] = pv;
        }
    };
    auto stage_B = [&](int buf, int ch) {
        const u16* srcH = whi + (size_t)ch * O * 64;
        const u16* srcL = wlo + (size_t)ch * O * 64;
        const u32 bH = sm + B_OFF + (buf * 2) * BPB;
        const u32 bL = bH + BPB;
        for (int s = tid; s < O * 8; s += 256) {
            int o = s >> 3, seg = s & 7;
            CP_ASYNC16(bH + o * 144 + seg * 16, srcH + o * 64 + seg * 8);
            CP_ASYNC16(bL + o * 144 + seg * 16, srcL + o * 64 + seg * 8);
        }
        CP_ASYNC_COMMIT();
    };
    auto stage_A = [&](int buf_a, int buf_x) {
        const u32* xb = xsp + buf_x * XROWS * XP;
        const u32 aH = sm + A_OFF + (buf_a * 2) * APB;
        const u32 aL = aH + APB;
#pragma unroll
        for (int uu = 0; uu < 2; uu++) {
            int t = tA + 32 * uu;
            u32 s[8];
#pragma unroll
            for (int e = 0; e < 8; e++) s[e] = xb[goff[e] + 2 * t];
            u32 ph[4], pl[4];
#pragma unroll
            for (int e2 = 0; e2 < 4; e2++) {
                ph[e2] = __byte_perm(s[2 * e2], s[2 * e2 + 1], 0x5410);
                pl[e2] = __byte_perm(s[2 * e2], s[2 * e2 + 1], 0x7632);
            }
            u32 off = (u32)(t * 144 + gA * 16);
            STS128(aH + off, ph[0], ph[1], ph[2], ph[3]);
            STS128(aL + off, pl[0], pl[1], pl[2], pl[3]);
        }
    };

    // ---- pipelined chunk loop ----------------------------------------------
    stage_B(0, 0);
    stage_x(0, 0);
    __syncthreads();
    stage_A(0, 0);

    for (int ch = 0; ch < NCH; ch++) {
        const int bf = ch & 1;
        if (ch + 1 < NCH) stage_x(1 - bf, ch + 1);
        CP_ASYNC_WAIT0();
        __syncthreads();
        if (ch + 1 < NCH) {
            stage_B(1 - bf, ch + 1);
            stage_A(1 - bf, 1 - bf);
        }
        // compute chunk ch from buffers [bf]
        const u32 ah_b = sm + A_OFF + (bf * 2) * APB + a_loff;
        const u32 al_b = ah_b + APB;
        const u32 bh_b = sm + B_OFF + (bf * 2) * BPB + b_loff;
        const u32 bl_b = bh_b + BPB;
#pragma unroll
        for (int ks = 0; ks < 4; ks++) {
            u32 ahi[4], alo[4];
            ldsm_x4(ahi, ah_b + ks * 32);
            ldsm_x4(alo, al_b + ks * 32);
            u32 bhi[NP][4], blo[NP][4];
#pragma unroll
            for (int p = 0; p < NP; p++) {
                ldsm_x4(bhi[p], bh_b + (u32)(p * 16 * 144) + ks * 32);
                ldsm_x4(blo[p], bl_b + (u32)(p * 16 * 144) + ks * 32);
            }
            // pass-major ordering: each acc reused every 2*NP MMAs
#pragma unroll
            for (int p = 0; p < NP; p++) {
                mma_bf16(acc[2 * p],     ahi, bhi[p]);
                mma_bf16(acc[2 * p + 1], ahi, bhi[p] + 2);
            }
#pragma unroll
            for (int p = 0; p < NP; p++) {
                mma_bf16(acc[2 * p],     ahi, blo[p]);
                mma_bf16(acc[2 * p + 1], ahi, blo[p] + 2);
            }
#pragma unroll
            for (int p = 0; p < NP; p++) {
                mma_bf16(acc[2 * p],     alo, bhi[p]);
                mma_bf16(acc[2 * p + 1], alo, bhi[p] + 2);
            }
        }
    }

    // ---- epilogue: frags -> smem (pitch DP) -> coalesced gmem --------------
    __syncthreads();
    float* Dt = reinterpret_cast<float*>(smem + 512);
    const int g = lane >> 2, c = lane & 3;
    const int r0 = 16 * mw + g;
#pragma unroll
    for (int nt = 0; nt < 2 * NP; nt++) {
        int n0 = nw * (O / 2) + nt * 8 + 2 * c;
        Dt[r0 * DP + n0]           = acc[nt][0];
        Dt[r0 * DP + n0 + 1]       = acc[nt][1];
        Dt[(r0 + 8) * DP + n0]     = acc[nt][2];
        Dt[(r0 + 8) * DP + n0 + 1] = acc[nt][3];
    }
    __syncthreads();
    for (int idx = tid; idx < O * 64; idx += 256) {
        int o = idx >> 6, tl = idx & 63;
        int t = t0 + tl;
        if (t < Tconv) {
            float v = Dt[tl * DP + o] + bias_sh[o];
            if (RELU) v = fmaxf(v, 0.f);
            size_t oi = ((size_t)b * O + o) * Tconv + t;
            if (OUT_PACKED) ((u32*)yv)[oi] = split1(v);
            else            ((float*)yv)[oi] = v;
        }
    }
}

// ---------------------------------------------------------------------------
// Masked adaptive-max over valid frames + 3-layer MLP head
// ---------------------------------------------------------------------------
__global__ void head_kernel(const float* __restrict__ y7,       // [64][128][14]
                            const int* __restrict__ len_mask,
                            const float* __restrict__ lw1, const float* __restrict__ lb1,
                            const float* __restrict__ lw2, const float* __restrict__ lb2,
                            const float* __restrict__ lw3, const float* __restrict__ lb3,
                            float* __restrict__ out) {
    __shared__ float v[128], h1[128], h2[64];
    const int b = blockIdx.x;
    const int tid = threadIdx.x;

    int L = len_mask[b];
    L = (L - 10) / 2 + 1;
    L = (L - 5) / 2 + 1;
    L = (L - 5) / 2 + 1;
    L = (L - 5) / 2 + 1;
    L >>= 1;
    L = (L - 5) / 2 + 1;
    L >>= 1;
    L = (L - 5) / 2 + 1;
    L = (L - 3) / 2 + 1;
    if (L > 14) L = 14;
    if (L < 1)  L = 1;

    const float* row = y7 + ((size_t)b * 128 + tid) * 14;
    float m = -3.4e38f;
    for (int t = 0; t < L; t++) m = fmaxf(m, row[t]);
    v[tid] = m;
    __syncthreads();

    float s = lb1[tid];
#pragma unroll 8
    for (int i = 0; i < 128; i++) s += lw1[tid * 128 + i] * v[i];
    h1[tid] = fmaxf(s, 0.f);
    __syncthreads();

    if (tid < 64) {
        float s2 = lb2[tid];
#pragma unroll 8
        for (int i = 0; i < 128; i++) s2 += lw2[tid * 128 + i] * h1[i];
        h2[tid] = fmaxf(s2, 0.f);
    }
    __syncthreads();

    if (tid < 5) {
        float s3 = lb3[tid];
#pragma unroll 8
        for (int i = 0; i < 64; i++) s3 += lw3[tid * 64 + i] * h2[i];
        out[b * 5 + tid] = s3;
    }
}

// ---------------------------------------------------------------------------
// Launch
// ---------------------------------------------------------------------------
extern "C" void kernel_launch(void* const* d_in, const int* in_sizes, int n_in,
                              void* d_out, int out_size) {
    const float* x    = (const float*)d_in[0];
    const int*   lenm = (const int*)d_in[1];
    const float* w1 = (const float*)d_in[2];  const float* b1 = (const float*)d_in[3];
    const float* w2 = (const float*)d_in[4];  const float* b2 = (const float*)d_in[5];
    const float* w3 = (const float*)d_in[6];  const float* b3 = (const float*)d_in[7];
    const float* w4 = (const float*)d_in[8];  const float* b4 = (const float*)d_in[9];
    const float* w5 = (const float*)d_in[10]; const float* b5 = (const float*)d_in[11];
    const float* w6 = (const float*)d_in[12]; const float* b6 = (const float*)d_in[13];
    const float* w7 = (const float*)d_in[14]; const float* b7 = (const float*)d_in[15];
    const float* lw1 = (const float*)d_in[16]; const float* lb1 = (const float*)d_in[17];
    const float* lw2 = (const float*)d_in[18]; const float* lb2 = (const float*)d_in[19];
    const float* lw3 = (const float*)d_in[20]; const float* lb3 = (const float*)d_in[21];

    u32* base = nullptr;
    cudaGetSymbolAddress((void**)&base, g_scratch);
    u16* wsp = nullptr;
    cudaGetSymbolAddress((void**)&wsp, g_wsplit);

    u32* B1 = base + OFF_B1;
    u32* B2 = base + OFF_B2;
    u32* B3 = base + OFF_B3;
    u32* B4 = base + OFF_B4;
    u32* B5 = base + OFF_B5;
    u32* B6 = base + OFF_B6;
    float* B7 = (float*)(base + OFF_B7);

    // kernels:                I   O    K  RELU  IN  OUTPK
    auto m1 = conv_hmma_kernel<40, 96, 10, true,  0, true>;
    auto m2 = conv_hmma_kernel<96, 96,  5, true,  1, true>;   // conv2, conv3
    auto m4 = conv_hmma_kernel<96, 96,  5, false, 1, true>;   // conv4
    auto m5 = conv_hmma_kernel<96, 96,  5, false, 2, true>;   // conv5 (pool in)
    auto m6 = conv_hmma_kernel<96, 96,  5, true,  2, true>;   // conv6 (pool in)
    auto m7 = conv_hmma_kernel<96, 128, 3, true,  1, false>;  // conv7 -> fp32

    const int SM1 = cx_smem(10, 96);
    const int SM2 = cx_smem(5, 96);
    const int SM7 = cx_smem(3, 128);
    cudaFuncSetAttribute(m1, cudaFuncAttributeMaxDynamicSharedMemorySize, SM1);
    cudaFuncSetAttribute(m2, cudaFuncAttributeMaxDynamicSharedMemorySize, SM2);
    cudaFuncSetAttribute(m4, cudaFuncAttributeMaxDynamicSharedMemorySize, SM2);
    cudaFuncSetAttribute(m5, cudaFuncAttributeMaxDynamicSharedMemorySize, SM2);
    cudaFuncSetAttribute(m6, cudaFuncAttributeMaxDynamicSharedMemorySize, SM2);
    cudaFuncSetAttribute(m7, cudaFuncAttributeMaxDynamicSharedMemorySize, SM7);

    // 0: weight pre-split (all 7 conv weights, chunked layout)
    presplit_w_kernel<<<(329728 + 255) / 256, 256>>>(w1, w2, w3, w4, w5, w6, w7);

    // 1-7: pipelined HMMA convs
    m1<<<dim3(64, 64), 256, SM1>>>(x,  wsp + W1H, wsp + W1L, b1, B1, 8192, 8192, 4092);
    m2<<<dim3(32, 64), 256, SM2>>>(B1, wsp + W2H, wsp + W2L, b2, B2, 4092, 4092, 2044);
    m2<<<dim3(16, 64), 256, SM2>>>(B2, wsp + W3H, wsp + W3L, b3, B3, 2044, 2044, 1020);
    m4<<<dim3(8, 64),  256, SM2>>>(B3, wsp + W4H, wsp + W4L, b4, B4, 1020, 1020, 508);
    m5<<<dim3(2, 64),  256, SM2>>>(B4, wsp + W5H, wsp + W5L, b5, B5, 254, 508, 125);
    m6<<<dim3(1, 64),  256, SM2>>>(B5, wsp + W6H, wsp + W6L, b6, B6, 62, 125, 29);
    m7<<<dim3(1, 64),  256, SM7>>>(B6, wsp + W7H, wsp + W7L, b7, B7, 29, 29, 14);

    // 8: masked max + MLP head
    head_kernel<<<64, 128>>>(B7, lenm, lw1, lb1, lw2, lb2, lw3, lb3,
                             (float*)d_out);
}

// round 10
// speedup vs baseline: 1.3789x; 1.3789x over previous
#include <cuda_runtime.h>
#include <cuda_bf16.h>
#include <cstdint>
#include <cstddef>

typedef unsigned long long u64;
typedef unsigned int u32;
typedef unsigned short u16;

// ---------------------------------------------------------------------------
// Scratch buffers (device globals; no allocations anywhere).
// B1..B6 hold packed bf16(hi,lo) u32 per element; B7 holds fp32.
// ---------------------------------------------------------------------------
static constexpr size_t S_B1 = 64ull * 96 * 4092;
static constexpr size_t S_B2 = 64ull * 96 * 2044;
static constexpr size_t S_B3 = 64ull * 96 * 1020;
static constexpr size_t S_B4 = 64ull * 96 * 508;
static constexpr size_t S_B5 = 64ull * 96 * 125;
static constexpr size_t S_B6 = 64ull * 96 * 29;
static constexpr size_t S_B7 = 64ull * 128 * 14;

static constexpr size_t OFF_B1 = 0;
static constexpr size_t OFF_B2 = OFF_B1 + S_B1;
static constexpr size_t OFF_B3 = OFF_B2 + S_B2;
static constexpr size_t OFF_B4 = OFF_B3 + S_B3;
static constexpr size_t OFF_B5 = OFF_B4 + S_B4;
static constexpr size_t OFF_B6 = OFF_B5 + S_B5;
static constexpr size_t OFF_B7 = OFF_B6 + S_B6;
static constexpr size_t SCRATCH_TOTAL = OFF_B7 + S_B7;

__device__ u32 g_scratch[SCRATCH_TOTAL];

// pre-split weights (bf16 hi/lo), layout [NCH][O][64] with chunk = CPC
// channels x K taps (c = li*K + k), zero-padded.
static constexpr int W1H = 0,      W1L = 43008;    // O=96  NCH=7 (CPC=6, K=10)
static constexpr int W2H = 86016,  W2L = 135168;   // O=96  NCH=8 (CPC=12, K=5)
static constexpr int W3H = 184320, W3L = 233472;
static constexpr int W4H = 282624, W4L = 331776;
static constexpr int W5H = 380928, W5L = 430080;
static constexpr int W6H = 479232, W6L = 528384;
static constexpr int W7H = 577536, W7L = 618496;   // O=128 NCH=5 (CPC=21, K=3)
__device__ __align__(256) u16 g_wsplit[659456];

// ---------------------------------------------------------------------------
// PTX helpers (baseline ISA only — compiles at compute_103)
// ---------------------------------------------------------------------------
__device__ __forceinline__ void ldsm_x4(u32* r, u32 addr) {
    asm volatile("ldmatrix.sync.aligned.m8n8.x4.shared.b16 {%0,%1,%2,%3}, [%4];"
                 : "=r"(r[0]), "=r"(r[1]), "=r"(r[2]), "=r"(r[3]) : "r"(addr));
}
__device__ __forceinline__ void mma_bf16(float* d, const u32* a, const u32* b) {
    asm volatile(
        "mma.sync.aligned.m16n8k16.row.col.f32.bf16.bf16.f32 "
        "{%0,%1,%2,%3}, {%4,%5,%6,%7}, {%8,%9}, {%0,%1,%2,%3};"
        : "+f"(d[0]), "+f"(d[1]), "+f"(d[2]), "+f"(d[3])
        : "r"(a[0]), "r"(a[1]), "r"(a[2]), "r"(a[3]), "r"(b[0]), "r"(b[1]));
}
#define CP_ASYNC16(dst, src) \
    asm volatile("cp.async.cg.shared.global [%0], [%1], 16;" \
                 :: "r"((u32)(dst)), "l"(src) : "memory")
#define CP_ASYNC_COMMIT() asm volatile("cp.async.commit_group;" ::: "memory")
#define CP_ASYNC_WAIT0()  asm volatile("cp.async.wait_group 0;" ::: "memory")
#define STS128(addr, a, b, c, d) \
    asm volatile("st.shared.v4.b32 [%0], {%1, %2, %3, %4};" \
                 :: "r"((u32)(addr)), "r"(a), "r"(b), "r"(c), "r"(d) : "memory")

__device__ __forceinline__ u32 smem_u32(const void* p) {
    u32 a;
    asm("{ .reg .u64 t; cvta.to.shared.u64 t, %1; cvt.u32.u64 %0, t; }"
        : "=r"(a) : "l"(p));
    return a;
}

// fp32 -> packed (bf16 hi | bf16 lo << 16), value ~= hi + lo
__device__ __forceinline__ u32 split1(float v) {
    __nv_bfloat16 h = __float2bfloat16_rn(v);
    __nv_bfloat16 l = __float2bfloat16_rn(v - __bfloat162float(h));
    return (u32)__bfloat16_as_ushort(h) | ((u32)__bfloat16_as_ushort(l) << 16);
}
__device__ __forceinline__ float unsplit1(u32 p) {
    return __bfloat162float(__ushort_as_bfloat16((u16)(p & 0xFFFF))) +
           __bfloat162float(__ushort_as_bfloat16((u16)(p >> 16)));
}

// layout constants (host + device agree). x is FULLY resident:
// XROWS = NCH*CPC + 1 rows (rows >= I zeroed so gather pads read 0-safe data)
__host__ __device__ constexpr int cx_cpc(int K)   { return 64 / K; }
__host__ __device__ constexpr int cx_nch(int I, int K) {
    return (I + cx_cpc(K) - 1) / cx_cpc(K);
}
__host__ __device__ constexpr int cx_uspan(int K) { return 128 + K; }
__host__ __device__ constexpr int cx_xp(int K)    { return (cx_uspan(K) + 3) & ~3; }
__host__ __device__ constexpr int cx_xrows(int I, int K) {
    return cx_nch(I, K) * cx_cpc(K) + 1;
}
__host__ __device__ constexpr int cx_aoff(int I, int K) {
    return (512 + cx_xrows(I, K) * cx_xp(K) * 4 + 15) & ~15;
}
__host__ __device__ constexpr int cx_boff(int I, int K) {
    return cx_aoff(I, K) + 2 * 64 * 144;     // A hi+lo, single buffer
}
__host__ __device__ constexpr int cx_smem(int I, int K, int O) {
    int total = cx_boff(I, K) + 2 * O * 144; // B hi+lo, single buffer
    int dmin = 512 + 64 * (O + 1) * 4;
    return total > dmin ? total : dmin;
}

// ---------------------------------------------------------------------------
// Weight pre-split into chunked layout [NCH][O][64], c = li*K + k
// ---------------------------------------------------------------------------
__global__ void presplit_w_kernel(
    const float* __restrict__ w1, const float* __restrict__ w2,
    const float* __restrict__ w3, const float* __restrict__ w4,
    const float* __restrict__ w5, const float* __restrict__ w6,
    const float* __restrict__ w7) {
    int n = blockIdx.x * blockDim.x + threadIdx.x;
    const float* w; int I, O, K; u16 *hi, *lo; int idx;
    if      (n < 43008)  { w = w1; I = 40; O = 96;  K = 10; hi = g_wsplit + W1H; lo = g_wsplit + W1L; idx = n; }
    else if (n < 92160)  { w = w2; I = 96; O = 96;  K = 5;  hi = g_wsplit + W2H; lo = g_wsplit + W2L; idx = n - 43008; }
    else if (n < 141312) { w = w3; I = 96; O = 96;  K = 5;  hi = g_wsplit + W3H; lo = g_wsplit + W3L; idx = n - 92160; }
    else if (n < 190464) { w = w4; I = 96; O = 96;  K = 5;  hi = g_wsplit + W4H; lo = g_wsplit + W4L; idx = n - 141312; }
    else if (n < 239616) { w = w5; I = 96; O = 96;  K = 5;  hi = g_wsplit + W5H; lo = g_wsplit + W5L; idx = n - 190464; }
    else if (n < 288768) { w = w6; I = 96; O = 96;  K = 5;  hi = g_wsplit + W6H; lo = g_wsplit + W6L; idx = n - 239616; }
    else if (n < 329728) { w = w7; I = 96; O = 128; K = 3;  hi = g_wsplit + W7H; lo = g_wsplit + W7L; idx = n - 288768; }
    else return;
    int CPC = 64 / K;
    int c  = idx & 63;
    int o  = (idx >> 6) % O;
    int ch = idx / (64 * O);
    int li = c / K;
    int k  = c - li * K;
    int i  = ch * CPC + li;
    float v = (li < CPC && i < I) ? w[(o * I + i) * K + k] : 0.f;
    u32 p = split1(v);
    hi[idx] = (u16)(p & 0xFFFF);
    lo[idx] = (u16)(p >> 16);
}

// ---------------------------------------------------------------------------
// Implicit-GEMM conv via HMMA, bf16 split, 3 passes. M tile = 64; x fully
// resident in smem (packed hi|lo u32); per-chunk: hoisted A gather (LDS from
// immutable xsp, overlaps prior chunk's tensor drain) -> barrier -> B
// cp.async + A STS -> wait+barrier -> pass-major compute. 8 warps =
// 4 m-warps x 2 n-warps; warp tile m16 x n(O/2). 2 CTAs/SM.
// IN_MODE: 0 = fp32 input, 1 = packed u32 input, 2 = packed + avgpool2 + relu
// ---------------------------------------------------------------------------
template <int I, int O, int K, bool RELU, int IN_MODE, bool OUT_PACKED>
__global__ __launch_bounds__(256, 2)
void conv_hmma_kernel(const void* __restrict__ xv,
                      const u16* __restrict__ whi, const u16* __restrict__ wlo,
                      const float* __restrict__ bias, void* __restrict__ yv,
                      int Tin, int TinRaw, int Tconv) {
    constexpr int CPC   = cx_cpc(K);
    constexpr int NCH   = cx_nch(I, K);
    constexpr int USPAN = cx_uspan(K);
    constexpr int XP    = cx_xp(K);
    constexpr int XROWS = cx_xrows(I, K);
    constexpr int A_OFF = cx_aoff(I, K);
    constexpr int B_OFF = cx_boff(I, K);
    constexpr int APB   = 64 * 144;          // one A tile bytes
    constexpr int BPB   = O * 144;           // one B tile bytes
    constexpr int NP    = O / 32;            // n-tile pairs per warp
    constexpr int DP    = O + 1;

    extern __shared__ char smem[];
    const u32 sm = smem_u32(smem);
    float* bias_sh = reinterpret_cast<float*>(smem);
    u32*   xsp     = reinterpret_cast<u32*>(smem + 512);   // [XROWS][XP]

    const int b    = blockIdx.y;
    const int t0   = blockIdx.x * 64;
    const int tid  = threadIdx.x;
    const int wid  = tid >> 5;
    const int lane = tid & 31;
    const int mw   = wid & 3;
    const int nw   = wid >> 2;
    const int tA   = tid >> 3;               // gather: time row (0..31)
    const int gA   = tid & 7;                // gather: 8-col group

    if (tid < O) bias_sh[tid] = bias[tid];

    // ---- stage full x slice once (packed u32), zero pad rows ---------------
    for (int n = tid; n < I * USPAN; n += 256) {
        int i = n / USPAN;
        int u = n - i * USPAN;
        int tg = 2 * t0 + u;
        u32 pv = 0;
        if (tg < Tin) {
            if (IN_MODE == 0) {
                const float* xf = (const float*)xv;
                pv = split1(xf[((size_t)b * I + i) * Tin + tg]);
            } else if (IN_MODE == 1) {
                const u32* xu = (const u32*)xv;
                pv = xu[((size_t)b * I + i) * Tin + tg];
            } else {
                const u32* xu = (const u32*)xv;
                const u32* row = xu + ((size_t)b * I + i) * TinRaw + 2 * tg;
                float f = 0.5f * (unsplit1(row[0]) + unsplit1(row[1]));
                pv = split1(fmaxf(f, 0.f));
            }
        }
        xsp[i * XP + u] = pv;
    }
    for (int n = tid; n < (XROWS - I) * XP; n += 256) xsp[I * XP + n] = 0;

    // chunk-invariant gather offsets (K is constexpr -> mul/shift, no IDIV)
    int goff[8];
#pragma unroll
    for (int e = 0; e < 8; e++) {
        int cg = gA * 8 + e;
        int li = cg / K;
        int k  = cg - li * K;
        goff[e] = li * XP + k;
    }

    // ldsm lane offsets
    const u32 a_loff = (u32)((16 * mw + (lane & 7) + ((lane >> 3) & 1) * 8) * 144
                             + (lane >> 4) * 16);
    const u32 b_loff = (u32)((nw * (O / 2) + ((lane >> 4) << 3) + (lane & 7)) * 144
                             + ((lane >> 3) & 1) * 16);

    float acc[2 * NP][4];
#pragma unroll
    for (int nt = 0; nt < 2 * NP; nt++)
#pragma unroll
        for (int q = 0; q < 4; q++) acc[nt][q] = 0.f;

    __syncthreads();   // xsp ready (immutable from here on)

    const u32 ah_b = sm + A_OFF + a_loff;
    const u32 al_b = ah_b + APB;
    const u32 bh_b = sm + B_OFF + b_loff;
    const u32 bl_b = bh_b + BPB;

    for (int ch = 0; ch < NCH; ch++) {
        // ---- A gather (LDS from immutable xsp) — hoisted before barrier ----
        u32 ph[2][4], pl[2][4];
        {
            const u32* xb = xsp + ch * (CPC * XP);
#pragma unroll
            for (int uu = 0; uu < 2; uu++) {
                int t2 = 2 * (tA + 32 * uu);
                u32 s[8];
#pragma unroll
                for (int e = 0; e < 8; e++) s[e] = xb[goff[e] + t2];
#pragma unroll
                for (int e2 = 0; e2 < 4; e2++) {
                    ph[uu][e2] = __byte_perm(s[2 * e2], s[2 * e2 + 1], 0x5410);
                    pl[uu][e2] = __byte_perm(s[2 * e2], s[2 * e2 + 1], 0x7632);
                }
            }
        }

        if (ch) __syncthreads();   // prior compute done reading A/B smem

        // ---- B: cp.async from pre-split gmem (L2-resident weights) ---------
        {
            const u16* srcH = whi + (size_t)ch * O * 64;
            const u16* srcL = wlo + (size_t)ch * O * 64;
            const u32 bH = sm + B_OFF;
            const u32 bL = bH + BPB;
            for (int s = tid; s < O * 8; s += 256) {
                int o = s >> 3, seg = s & 7;
                CP_ASYNC16(bH + o * 144 + seg * 16, srcH + o * 64 + seg * 8);
                CP_ASYNC16(bL + o * 144 + seg * 16, srcL + o * 64 + seg * 8);
            }
            CP_ASYNC_COMMIT();
        }

        // ---- A: store gathered frags ---------------------------------------
        {
            const u32 aH = sm + A_OFF;
            const u32 aL = aH + APB;
#pragma unroll
            for (int uu = 0; uu < 2; uu++) {
                u32 off = (u32)((tA + 32 * uu) * 144 + gA * 16);
                STS128(aH + off, ph[uu][0], ph[uu][1], ph[uu][2], ph[uu][3]);
                STS128(aL + off, pl[uu][0], pl[uu][1], pl[uu][2], pl[uu][3]);
            }
        }

        CP_ASYNC_WAIT0();
        __syncthreads();

        // ---- compute: 4 k-steps; pass-major (acc reuse distance = 2*NP) ----
#pragma unroll
        for (int ks = 0; ks < 4; ks++) {
            u32 ahi[4], alo[4];
            ldsm_x4(ahi, ah_b + ks * 32);
            ldsm_x4(alo, al_b + ks * 32);
            u32 bhi[NP][4], blo[NP][4];
#pragma unroll
            for (int p = 0; p < NP; p++) {
                ldsm_x4(bhi[p], bh_b + (u32)(p * 16 * 144) + ks * 32);
                ldsm_x4(blo[p], bl_b + (u32)(p * 16 * 144) + ks * 32);
            }
#pragma unroll
            for (int p = 0; p < NP; p++) {
                mma_bf16(acc[2 * p],     ahi, bhi[p]);
                mma_bf16(acc[2 * p + 1], ahi, bhi[p] + 2);
            }
#pragma unroll
            for (int p = 0; p < NP; p++) {
                mma_bf16(acc[2 * p],     ahi, blo[p]);
                mma_bf16(acc[2 * p + 1], ahi, blo[p] + 2);
            }
#pragma unroll
            for (int p = 0; p < NP; p++) {
                mma_bf16(acc[2 * p],     alo, bhi[p]);
                mma_bf16(acc[2 * p + 1], alo, bhi[p] + 2);
            }
        }
    }

    // ---- epilogue: frags -> smem (pitch DP) -> coalesced gmem --------------
    __syncthreads();
    float* Dt = reinterpret_cast<float*>(smem + 512);
    const int g = lane >> 2, c = lane & 3;
    const int r0 = 16 * mw + g;
#pragma unroll
    for (int nt = 0; nt < 2 * NP; nt++) {
        int n0 = nw * (O / 2) + nt * 8 + 2 * c;
        Dt[r0 * DP + n0]           = acc[nt][0];
        Dt[r0 * DP + n0 + 1]       = acc[nt][1];
        Dt[(r0 + 8) * DP + n0]     = acc[nt][2];
        Dt[(r0 + 8) * DP + n0 + 1] = acc[nt][3];
    }
    __syncthreads();
    for (int idx = tid; idx < O * 64; idx += 256) {
        int o = idx >> 6, tl = idx & 63;
        int t = t0 + tl;
        if (t < Tconv) {
            float v = Dt[tl * DP + o] + bias_sh[o];
            if (RELU) v = fmaxf(v, 0.f);
            size_t oi = ((size_t)b * O + o) * Tconv + t;
            if (OUT_PACKED) ((u32*)yv)[oi] = split1(v);
            else            ((float*)yv)[oi] = v;
        }
    }
}

// ---------------------------------------------------------------------------
// Masked adaptive-max over valid frames + 3-layer MLP head
// ---------------------------------------------------------------------------
__global__ void head_kernel(const float* __restrict__ y7,       // [64][128][14]
                            const int* __restrict__ len_mask,
                            const float* __restrict__ lw1, const float* __restrict__ lb1,
                            const float* __restrict__ lw2, const float* __restrict__ lb2,
                            const float* __restrict__ lw3, const float* __restrict__ lb3,
                            float* __restrict__ out) {
    __shared__ float v[128], h1[128], h2[64];
    const int b = blockIdx.x;
    const int tid = threadIdx.x;

    int L = len_mask[b];
    L = (L - 10) / 2 + 1;
    L = (L - 5) / 2 + 1;
    L = (L - 5) / 2 + 1;
    L = (L - 5) / 2 + 1;
    L >>= 1;
    L = (L - 5) / 2 + 1;
    L >>= 1;
    L = (L - 5) / 2 + 1;
    L = (L - 3) / 2 + 1;
    if (L > 14) L = 14;
    if (L < 1)  L = 1;

    const float* row = y7 + ((size_t)b * 128 + tid) * 14;
    float m = -3.4e38f;
    for (int t = 0; t < L; t++) m = fmaxf(m, row[t]);
    v[tid] = m;
    __syncthreads();

    float s = lb1[tid];
#pragma unroll 8
    for (int i = 0; i < 128; i++) s += lw1[tid * 128 + i] * v[i];
    h1[tid] = fmaxf(s, 0.f);
    __syncthreads();

    if (tid < 64) {
        float s2 = lb2[tid];
#pragma unroll 8
        for (int i = 0; i < 128; i++) s2 += lw2[tid * 128 + i] * h1[i];
        h2[tid] = fmaxf(s2, 0.f);
    }
    __syncthreads();

    if (tid < 5) {
        float s3 = lb3[tid];
#pragma unroll 8
        for (int i = 0; i < 64; i++) s3 += lw3[tid * 64 + i] * h2[i];
        out[b * 5 + tid] = s3;
    }
}

// ---------------------------------------------------------------------------
// Launch
// ---------------------------------------------------------------------------
extern "C" void kernel_launch(void* const* d_in, const int* in_sizes, int n_in,
                              void* d_out, int out_size) {
    const float* x    = (const float*)d_in[0];
    const int*   lenm = (const int*)d_in[1];
    const float* w1 = (const float*)d_in[2];  const float* b1 = (const float*)d_in[3];
    const float* w2 = (const float*)d_in[4];  const float* b2 = (const float*)d_in[5];
    const float* w3 = (const float*)d_in[6];  const float* b3 = (const float*)d_in[7];
    const float* w4 = (const float*)d_in[8];  const float* b4 = (const float*)d_in[9];
    const float* w5 = (const float*)d_in[10]; const float* b5 = (const float*)d_in[11];
    const float* w6 = (const float*)d_in[12]; const float* b6 = (const float*)d_in[13];
    const float* w7 = (const float*)d_in[14]; const float* b7 = (const float*)d_in[15];
    const float* lw1 = (const float*)d_in[16]; const float* lb1 = (const float*)d_in[17];
    const float* lw2 = (const float*)d_in[18]; const float* lb2 = (const float*)d_in[19];
    const float* lw3 = (const float*)d_in[20]; const float* lb3 = (const float*)d_in[21];

    u32* base = nullptr;
    cudaGetSymbolAddress((void**)&base, g_scratch);
    u16* wsp = nullptr;
    cudaGetSymbolAddress((void**)&wsp, g_wsplit);

    u32* B1 = base + OFF_B1;
    u32* B2 = base + OFF_B2;
    u32* B3 = base + OFF_B3;
    u32* B4 = base + OFF_B4;
    u32* B5 = base + OFF_B5;
    u32* B6 = base + OFF_B6;
    float* B7 = (float*)(base + OFF_B7);

    // kernels:                I   O    K  RELU  IN  OUTPK
    auto m1 = conv_hmma_kernel<40, 96, 10, true,  0, true>;
    auto m2 = conv_hmma_kernel<96, 96,  5, true,  1, true>;   // conv2, conv3
    auto m4 = conv_hmma_kernel<96, 96,  5, false, 1, true>;   // conv4
    auto m5 = conv_hmma_kernel<96, 96,  5, false, 2, true>;   // conv5 (pool in)
    auto m6 = conv_hmma_kernel<96, 96,  5, true,  2, true>;   // conv6 (pool in)
    auto m7 = conv_hmma_kernel<96, 128, 3, true,  1, false>;  // conv7 -> fp32

    const int SM1 = cx_smem(40, 10, 96);
    const int SM2 = cx_smem(96, 5, 96);
    const int SM7 = cx_smem(96, 3, 128);
    cudaFuncSetAttribute(m1, cudaFuncAttributeMaxDynamicSharedMemorySize, SM1);
    cudaFuncSetAttribute(m2, cudaFuncAttributeMaxDynamicSharedMemorySize, SM2);
    cudaFuncSetAttribute(m4, cudaFuncAttributeMaxDynamicSharedMemorySize, SM2);
    cudaFuncSetAttribute(m5, cudaFuncAttributeMaxDynamicSharedMemorySize, SM2);
    cudaFuncSetAttribute(m6, cudaFuncAttributeMaxDynamicSharedMemorySize, SM2);
    cudaFuncSetAttribute(m7, cudaFuncAttributeMaxDynamicSharedMemorySize, SM7);

    // 0: weight pre-split (all 7 conv weights, chunked layout)
    presplit_w_kernel<<<(329728 + 255) / 256, 256>>>(w1, w2, w3, w4, w5, w6, w7);

    // 1-7: HMMA convs
    m1<<<dim3(64, 64), 256, SM1>>>(x,  wsp + W1H, wsp + W1L, b1, B1, 8192, 8192, 4092);
    m2<<<dim3(32, 64), 256, SM2>>>(B1, wsp + W2H, wsp + W2L, b2, B2, 4092, 4092, 2044);
    m2<<<dim3(16, 64), 256, SM2>>>(B2, wsp + W3H, wsp + W3L, b3, B3, 2044, 2044, 1020);
    m4<<<dim3(8, 64),  256, SM2>>>(B3, wsp + W4H, wsp + W4L, b4, B4, 1020, 1020, 508);
    m5<<<dim3(2, 64),  256, SM2>>>(B4, wsp + W5H, wsp + W5L, b5, B5, 254, 508, 125);
    m6<<<dim3(1, 64),  256, SM2>>>(B5, wsp + W6H, wsp + W6L, b6, B6, 62, 125, 29);
    m7<<<dim3(1, 64),  256, SM7>>>(B6, wsp + W7H, wsp + W7L, b7, B7, 29, 29, 14);

    // 8: masked max + MLP head
    head_kernel<<<64, 128>>>(B7, lenm, lw1, lb1, lw2, lb2, lw3, lb3,
                             (float*)d_out);
}

// round 11
// speedup vs baseline: 1.3815x; 1.0019x over previous
#include <cuda_runtime.h>
#include <cuda_bf16.h>
#include <cstdint>
#include <cstddef>

typedef unsigned long long u64;
typedef unsigned int u32;
typedef unsigned short u16;

// ---------------------------------------------------------------------------
// Scratch buffers (device globals; no allocations anywhere).
// B1..B6 hold packed bf16(hi,lo) u32 per element; B7 holds fp32.
// ---------------------------------------------------------------------------
static constexpr size_t S_B1 = 64ull * 96 * 4092;
static constexpr size_t S_B2 = 64ull * 96 * 2044;
static constexpr size_t S_B3 = 64ull * 96 * 1020;
static constexpr size_t S_B4 = 64ull * 96 * 508;
static constexpr size_t S_B5 = 64ull * 96 * 125;
static constexpr size_t S_B6 = 64ull * 96 * 29;
static constexpr size_t S_B7 = 64ull * 128 * 14;

static constexpr size_t OFF_B1 = 0;
static constexpr size_t OFF_B2 = OFF_B1 + S_B1;
static constexpr size_t OFF_B3 = OFF_B2 + S_B2;
static constexpr size_t OFF_B4 = OFF_B3 + S_B3;
static constexpr size_t OFF_B5 = OFF_B4 + S_B4;
static constexpr size_t OFF_B6 = OFF_B5 + S_B5;
static constexpr size_t OFF_B7 = OFF_B6 + S_B6;
static constexpr size_t SCRATCH_TOTAL = OFF_B7 + S_B7;

__device__ u32 g_scratch[SCRATCH_TOTAL];

// pre-split weights (bf16 hi/lo), layout [NCH][O][64] with chunk = CPC
// channels x K taps (c = li*K + k), zero-padded.
static constexpr int W1H = 0,      W1L = 43008;    // O=96  NCH=7 (CPC=6, K=10)
static constexpr int W2H = 86016,  W2L = 135168;   // O=96  NCH=8 (CPC=12, K=5)
static constexpr int W3H = 184320, W3L = 233472;
static constexpr int W4H = 282624, W4L = 331776;
static constexpr int W5H = 380928, W5L = 430080;
static constexpr int W6H = 479232, W6L = 528384;
static constexpr int W7H = 577536, W7L = 618496;   // O=128 NCH=5 (CPC=21, K=3)
__device__ __align__(256) u16 g_wsplit[659456];

// ---------------------------------------------------------------------------
// PTX helpers (baseline ISA only — compiles at compute_103)
// ---------------------------------------------------------------------------
__device__ __forceinline__ void ldsm_x4(u32* r, u32 addr) {
    asm volatile("ldmatrix.sync.aligned.m8n8.x4.shared.b16 {%0,%1,%2,%3}, [%4];"
                 : "=r"(r[0]), "=r"(r[1]), "=r"(r[2]), "=r"(r[3]) : "r"(addr));
}
__device__ __forceinline__ void mma_bf16(float* d, const u32* a, const u32* b) {
    asm volatile(
        "mma.sync.aligned.m16n8k16.row.col.f32.bf16.bf16.f32 "
        "{%0,%1,%2,%3}, {%4,%5,%6,%7}, {%8,%9}, {%0,%1,%2,%3};"
        : "+f"(d[0]), "+f"(d[1]), "+f"(d[2]), "+f"(d[3])
        : "r"(a[0]), "r"(a[1]), "r"(a[2]), "r"(a[3]), "r"(b[0]), "r"(b[1]));
}
#define CP_ASYNC16(dst, src) \
    asm volatile("cp.async.cg.shared.global [%0], [%1], 16;" \
                 :: "r"((u32)(dst)), "l"(src) : "memory")
#define CP_ASYNC_COMMIT() asm volatile("cp.async.commit_group;" ::: "memory")
#define CP_ASYNC_WAIT0()  asm volatile("cp.async.wait_group 0;" ::: "memory")
#define STS128(addr, a, b, c, d) \
    asm volatile("st.shared.v4.b32 [%0], {%1, %2, %3, %4};" \
                 :: "r"((u32)(addr)), "r"(a), "r"(b), "r"(c), "r"(d) : "memory")

__device__ __forceinline__ u32 smem_u32(const void* p) {
    u32 a;
    asm("{ .reg .u64 t; cvta.to.shared.u64 t, %1; cvt.u32.u64 %0, t; }"
        : "=r"(a) : "l"(p));
    return a;
}

// fp32 -> packed (bf16 hi | bf16 lo << 16), value ~= hi + lo
__device__ __forceinline__ u32 split1(float v) {
    __nv_bfloat16 h = __float2bfloat16_rn(v);
    __nv_bfloat16 l = __float2bfloat16_rn(v - __bfloat162float(h));
    return (u32)__bfloat16_as_ushort(h) | ((u32)__bfloat16_as_ushort(l) << 16);
}
__device__ __forceinline__ float unsplit1(u32 p) {
    return __bfloat162float(__ushort_as_bfloat16((u16)(p & 0xFFFF))) +
           __bfloat162float(__ushort_as_bfloat16((u16)(p >> 16)));
}

// layout constants (host + device agree). x is FULLY resident:
// XROWS = NCH*CPC + 1 rows (rows >= I zeroed so gather pads read 0-safe data)
__host__ __device__ constexpr int cx_cpc(int K)   { return 64 / K; }
__host__ __device__ constexpr int cx_nch(int I, int K) {
    return (I + cx_cpc(K) - 1) / cx_cpc(K);
}
__host__ __device__ constexpr int cx_uspan(int K) { return 128 + K; }
__host__ __device__ constexpr int cx_xp(int K)    { return (cx_uspan(K) + 3) & ~3; }
__host__ __device__ constexpr int cx_xrows(int I, int K) {
    return cx_nch(I, K) * cx_cpc(K) + 1;
}
__host__ __device__ constexpr int cx_aoff(int I, int K) {
    return (512 + cx_xrows(I, K) * cx_xp(K) * 4 + 15) & ~15;
}
__host__ __device__ constexpr int cx_boff(int I, int K) {
    return cx_aoff(I, K) + 2 * 64 * 144;     // A hi+lo, single buffer
}
__host__ __device__ constexpr int cx_smem(int I, int K, int O) {
    int total = cx_boff(I, K) + 2 * O * 144; // B hi+lo, single buffer
    int dmin = 512 + 64 * (O + 1) * 4;
    return total > dmin ? total : dmin;
}

// ---------------------------------------------------------------------------
// Weight pre-split into chunked layout [NCH][O][64], c = li*K + k
// ---------------------------------------------------------------------------
__global__ void presplit_w_kernel(
    const float* __restrict__ w1, const float* __restrict__ w2,
    const float* __restrict__ w3, const float* __restrict__ w4,
    const float* __restrict__ w5, const float* __restrict__ w6,
    const float* __restrict__ w7) {
    int n = blockIdx.x * blockDim.x + threadIdx.x;
    const float* w; int I, O, K; u16 *hi, *lo; int idx;
    if      (n < 43008)  { w = w1; I = 40; O = 96;  K = 10; hi = g_wsplit + W1H; lo = g_wsplit + W1L; idx = n; }
    else if (n < 92160)  { w = w2; I = 96; O = 96;  K = 5;  hi = g_wsplit + W2H; lo = g_wsplit + W2L; idx = n - 43008; }
    else if (n < 141312) { w = w3; I = 96; O = 96;  K = 5;  hi = g_wsplit + W3H; lo = g_wsplit + W3L; idx = n - 92160; }
    else if (n < 190464) { w = w4; I = 96; O = 96;  K = 5;  hi = g_wsplit + W4H; lo = g_wsplit + W4L; idx = n - 141312; }
    else if (n < 239616) { w = w5; I = 96; O = 96;  K = 5;  hi = g_wsplit + W5H; lo = g_wsplit + W5L; idx = n - 190464; }
    else if (n < 288768) { w = w6; I = 96; O = 96;  K = 5;  hi = g_wsplit + W6H; lo = g_wsplit + W6L; idx = n - 239616; }
    else if (n < 329728) { w = w7; I = 96; O = 128; K = 3;  hi = g_wsplit + W7H; lo = g_wsplit + W7L; idx = n - 288768; }
    else return;
    int CPC = 64 / K;
    int c  = idx & 63;
    int o  = (idx >> 6) % O;
    int ch = idx / (64 * O);
    int li = c / K;
    int k  = c - li * K;
    int i  = ch * CPC + li;
    float v = (li < CPC && i < I) ? w[(o * I + i) * K + k] : 0.f;
    u32 p = split1(v);
    hi[idx] = (u16)(p & 0xFFFF);
    lo[idx] = (u16)(p >> 16);
}

// ---------------------------------------------------------------------------
// Implicit-GEMM conv via HMMA, bf16 split, 3 passes. M tile = 64; x fully
// resident in smem (packed hi|lo u32); per-chunk: hoisted A gather (LDS from
// immutable xsp, overlaps prior chunk's tensor drain) -> barrier -> B
// cp.async + A STS -> wait+barrier -> pass-major compute. 8 warps =
// 4 m-warps x 2 n-warps; warp tile m16 x n(O/2). 2 CTAs/SM.
// IN_MODE: 0 = fp32 input, 1 = packed u32 input, 2 = packed + avgpool2 + relu
// ---------------------------------------------------------------------------
template <int I, int O, int K, bool RELU, int IN_MODE, bool OUT_PACKED>
__global__ __launch_bounds__(256, 2)
void conv_hmma_kernel(const void* __restrict__ xv,
                      const u16* __restrict__ whi, const u16* __restrict__ wlo,
                      const float* __restrict__ bias, void* __restrict__ yv,
                      int Tin, int TinRaw, int Tconv) {
    constexpr int CPC   = cx_cpc(K);
    constexpr int NCH   = cx_nch(I, K);
    constexpr int USPAN = cx_uspan(K);
    constexpr int XP    = cx_xp(K);
    constexpr int XROWS = cx_xrows(I, K);
    constexpr int A_OFF = cx_aoff(I, K);
    constexpr int B_OFF = cx_boff(I, K);
    constexpr int APB   = 64 * 144;          // one A tile bytes
    constexpr int BPB   = O * 144;           // one B tile bytes
    constexpr int NP    = O / 32;            // n-tile pairs per warp
    constexpr int DP    = O + 1;

    extern __shared__ char smem[];
    const u32 sm = smem_u32(smem);
    float* bias_sh = reinterpret_cast<float*>(smem);
    u32*   xsp     = reinterpret_cast<u32*>(smem + 512);   // [XROWS][XP]

    const int b    = blockIdx.y;
    const int t0   = blockIdx.x * 64;
    const int tid  = threadIdx.x;
    const int wid  = tid >> 5;
    const int lane = tid & 31;
    const int mw   = wid & 3;
    const int nw   = wid >> 2;
    const int tA   = tid >> 3;               // gather: time row (0..31)
    const int gA   = tid & 7;                // gather: 8-col group

    if (tid < O) bias_sh[tid] = bias[tid];

    // ---- stage full x slice once (packed u32), zero pad rows ---------------
    for (int n = tid; n < I * USPAN; n += 256) {
        int i = n / USPAN;
        int u = n - i * USPAN;
        int tg = 2 * t0 + u;
        u32 pv = 0;
        if (tg < Tin) {
            if (IN_MODE == 0) {
                const float* xf = (const float*)xv;
                pv = split1(xf[((size_t)b * I + i) * Tin + tg]);
            } else if (IN_MODE == 1) {
                const u32* xu = (const u32*)xv;
                pv = xu[((size_t)b * I + i) * Tin + tg];
            } else {
                const u32* xu = (const u32*)xv;
                const u32* row = xu + ((size_t)b * I + i) * TinRaw + 2 * tg;
                float f = 0.5f * (unsplit1(row[0]) + unsplit1(row[1]));
                pv = split1(fmaxf(f, 0.f));
            }
        }
        xsp[i * XP + u] = pv;
    }
    for (int n = tid; n < (XROWS - I) * XP; n += 256) xsp[I * XP + n] = 0;

    // chunk-invariant gather offsets (K is constexpr -> mul/shift, no IDIV)
    int goff[8];
#pragma unroll
    for (int e = 0; e < 8; e++) {
        int cg = gA * 8 + e;
        int li = cg / K;
        int k  = cg - li * K;
        goff[e] = li * XP + k;
    }

    // ldsm lane offsets
    const u32 a_loff = (u32)((16 * mw + (lane & 7) + ((lane >> 3) & 1) * 8) * 144
                             + (lane >> 4) * 16);
    const u32 b_loff = (u32)((nw * (O / 2) + ((lane >> 4) << 3) + (lane & 7)) * 144
                             + ((lane >> 3) & 1) * 16);

    float acc[2 * NP][4];
#pragma unroll
    for (int nt = 0; nt < 2 * NP; nt++)
#pragma unroll
        for (int q = 0; q < 4; q++) acc[nt][q] = 0.f;

    __syncthreads();   // xsp ready (immutable from here on)

    const u32 ah_b = sm + A_OFF + a_loff;
    const u32 al_b = ah_b + APB;
    const u32 bh_b = sm + B_OFF + b_loff;
    const u32 bl_b = bh_b + BPB;

    for (int ch = 0; ch < NCH; ch++) {
        // ---- A gather (LDS from immutable xsp) — hoisted before barrier ----
        u32 ph[2][4], pl[2][4];
        {
            const u32* xb = xsp + ch * (CPC * XP);
#pragma unroll
            for (int uu = 0; uu < 2; uu++) {
                int t2 = 2 * (tA + 32 * uu);
                u32 s[8];
#pragma unroll
                for (int e = 0; e < 8; e++) s[e] = xb[goff[e] + t2];
#pragma unroll
                for (int e2 = 0; e2 < 4; e2++) {
                    ph[uu][e2] = __byte_perm(s[2 * e2], s[2 * e2 + 1], 0x5410);
                    pl[uu][e2] = __byte_perm(s[2 * e2], s[2 * e2 + 1], 0x7632);
                }
            }
        }

        if (ch) __syncthreads();   // prior compute done reading A/B smem

        // ---- B: cp.async from pre-split gmem (L2-resident weights) ---------
        {
            const u16* srcH = whi + (size_t)ch * O * 64;
            const u16* srcL = wlo + (size_t)ch * O * 64;
            const u32 bH = sm + B_OFF;
            const u32 bL = bH + BPB;
            for (int s = tid; s < O * 8; s += 256) {
                int o = s >> 3, seg = s & 7;
                CP_ASYNC16(bH + o * 144 + seg * 16, srcH + o * 64 + seg * 8);
                CP_ASYNC16(bL + o * 144 + seg * 16, srcL + o * 64 + seg * 8);
            }
            CP_ASYNC_COMMIT();
        }

        // ---- A: store gathered frags ---------------------------------------
        {
            const u32 aH = sm + A_OFF;
            const u32 aL = aH + APB;
#pragma unroll
            for (int uu = 0; uu < 2; uu++) {
                u32 off = (u32)((tA + 32 * uu) * 144 + gA * 16);
                STS128(aH + off, ph[uu][0], ph[uu][1], ph[uu][2], ph[uu][3]);
                STS128(aL + off, pl[uu][0], pl[uu][1], pl[uu][2], pl[uu][3]);
            }
        }

        CP_ASYNC_WAIT0();
        __syncthreads();

        // ---- compute: 4 k-steps; pass-major (acc reuse distance = 2*NP) ----
#pragma unroll
        for (int ks = 0; ks < 4; ks++) {
            u32 ahi[4], alo[4];
            ldsm_x4(ahi, ah_b + ks * 32);
            ldsm_x4(alo, al_b + ks * 32);
            u32 bhi[NP][4], blo[NP][4];
#pragma unroll
            for (int p = 0; p < NP; p++) {
                ldsm_x4(bhi[p], bh_b + (u32)(p * 16 * 144) + ks * 32);
                ldsm_x4(blo[p], bl_b + (u32)(p * 16 * 144) + ks * 32);
            }
#pragma unroll
            for (int p = 0; p < NP; p++) {
                mma_bf16(acc[2 * p],     ahi, bhi[p]);
                mma_bf16(acc[2 * p + 1], ahi, bhi[p] + 2);
            }
#pragma unroll
            for (int p = 0; p < NP; p++) {
                mma_bf16(acc[2 * p],     ahi, blo[p]);
                mma_bf16(acc[2 * p + 1], ahi, blo[p] + 2);
            }
#pragma unroll
            for (int p = 0; p < NP; p++) {
                mma_bf16(acc[2 * p],     alo, bhi[p]);
                mma_bf16(acc[2 * p + 1], alo, bhi[p] + 2);
            }
        }
    }

    // ---- epilogue: frags -> smem (pitch DP) -> coalesced gmem --------------
    __syncthreads();
    float* Dt = reinterpret_cast<float*>(smem + 512);
    const int g = lane >> 2, c = lane & 3;
    const int r0 = 16 * mw + g;
#pragma unroll
    for (int nt = 0; nt < 2 * NP; nt++) {
        int n0 = nw * (O / 2) + nt * 8 + 2 * c;
        Dt[r0 * DP + n0]           = acc[nt][0];
        Dt[r0 * DP + n0 + 1]       = acc[nt][1];
        Dt[(r0 + 8) * DP + n0]     = acc[nt][2];
        Dt[(r0 + 8) * DP + n0 + 1] = acc[nt][3];
    }
    __syncthreads();
    for (int idx = tid; idx < O * 64; idx += 256) {
        int o = idx >> 6, tl = idx & 63;
        int t = t0 + tl;
        if (t < Tconv) {
            float v = Dt[tl * DP + o] + bias_sh[o];
            if (RELU) v = fmaxf(v, 0.f);
            size_t oi = ((size_t)b * O + o) * Tconv + t;
            if (OUT_PACKED) ((u32*)yv)[oi] = split1(v);
            else            ((float*)yv)[oi] = v;
        }
    }
}

// ---------------------------------------------------------------------------
// Masked adaptive-max over valid frames + 3-layer MLP head
// ---------------------------------------------------------------------------
__global__ void head_kernel(const float* __restrict__ y7,       // [64][128][14]
                            const int* __restrict__ len_mask,
                            const float* __restrict__ lw1, const float* __restrict__ lb1,
                            const float* __restrict__ lw2, const float* __restrict__ lb2,
                            const float* __restrict__ lw3, const float* __restrict__ lb3,
                            float* __restrict__ out) {
    __shared__ float v[128], h1[128], h2[64];
    const int b = blockIdx.x;
    const int tid = threadIdx.x;

    int L = len_mask[b];
    L = (L - 10) / 2 + 1;
    L = (L - 5) / 2 + 1;
    L = (L - 5) / 2 + 1;
    L = (L - 5) / 2 + 1;
    L >>= 1;
    L = (L - 5) / 2 + 1;
    L >>= 1;
    L = (L - 5) / 2 + 1;
    L = (L - 3) / 2 + 1;
    if (L > 14) L = 14;
    if (L < 1)  L = 1;

    const float* row = y7 + ((size_t)b * 128 + tid) * 14;
    float m = -3.4e38f;
    for (int t = 0; t < L; t++) m = fmaxf(m, row[t]);
    v[tid] = m;
    __syncthreads();

    float s = lb1[tid];
#pragma unroll 8
    for (int i = 0; i < 128; i++) s += lw1[tid * 128 + i] * v[i];
    h1[tid] = fmaxf(s, 0.f);
    __syncthreads();

    if (tid < 64) {
        float s2 = lb2[tid];
#pragma unroll 8
        for (int i = 0; i < 128; i++) s2 += lw2[tid * 128 + i] * h1[i];
        h2[tid] = fmaxf(s2, 0.f);
    }
    __syncthreads();

    if (tid < 5) {
        float s3 = lb3[tid];
#pragma unroll 8
        for (int i = 0; i < 64; i++) s3 += lw3[tid * 64 + i] * h2[i];
        out[b * 5 + tid] = s3;
    }
}

// ---------------------------------------------------------------------------
// Launch
// ---------------------------------------------------------------------------
extern "C" void kernel_launch(void* const* d_in, const int* in_sizes, int n_in,
                              void* d_out, int out_size) {
    const float* x    = (const float*)d_in[0];
    const int*   lenm = (const int*)d_in[1];
    const float* w1 = (const float*)d_in[2];  const float* b1 = (const float*)d_in[3];
    const float* w2 = (const float*)d_in[4];  const float* b2 = (const float*)d_in[5];
    const float* w3 = (const float*)d_in[6];  const float* b3 = (const float*)d_in[7];
    const float* w4 = (const float*)d_in[8];  const float* b4 = (const float*)d_in[9];
    const float* w5 = (const float*)d_in[10]; const float* b5 = (const float*)d_in[11];
    const float* w6 = (const float*)d_in[12]; const float* b6 = (const float*)d_in[13];
    const float* w7 = (const float*)d_in[14]; const float* b7 = (const float*)d_in[15];
    const float* lw1 = (const float*)d_in[16]; const float* lb1 = (const float*)d_in[17];
    const float* lw2 = (const float*)d_in[18]; const float* lb2 = (const float*)d_in[19];
    const float* lw3 = (const float*)d_in[20]; const float* lb3 = (const float*)d_in[21];

    u32* base = nullptr;
    cudaGetSymbolAddress((void**)&base, g_scratch);
    u16* wsp = nullptr;
    cudaGetSymbolAddress((void**)&wsp, g_wsplit);

    u32* B1 = base + OFF_B1;
    u32* B2 = base + OFF_B2;
    u32* B3 = base + OFF_B3;
    u32* B4 = base + OFF_B4;
    u32* B5 = base + OFF_B5;
    u32* B6 = base + OFF_B6;
    float* B7 = (float*)(base + OFF_B7);

    // kernels:                I   O    K  RELU  IN  OUTPK
    auto m1 = conv_hmma_kernel<40, 96, 10, true,  0, true>;
    auto m2 = conv_hmma_kernel<96, 96,  5, true,  1, true>;   // conv2, conv3
    auto m4 = conv_hmma_kernel<96, 96,  5, false, 1, true>;   // conv4
    auto m5 = conv_hmma_kernel<96, 96,  5, false, 2, true>;   // conv5 (pool in)
    auto m6 = conv_hmma_kernel<96, 96,  5, true,  2, true>;   // conv6 (pool in)
    auto m7 = conv_hmma_kernel<96, 128, 3, true,  1, false>;  // conv7 -> fp32

    const int SM1 = cx_smem(40, 10, 96);
    const int SM2 = cx_smem(96, 5, 96);
    const int SM7 = cx_smem(96, 3, 128);
    cudaFuncSetAttribute(m1, cudaFuncAttributeMaxDynamicSharedMemorySize, SM1);
    cudaFuncSetAttribute(m2, cudaFuncAttributeMaxDynamicSharedMemorySize, SM2);
    cudaFuncSetAttribute(m4, cudaFuncAttributeMaxDynamicSharedMemorySize, SM2);
    cudaFuncSetAttribute(m5, cudaFuncAttributeMaxDynamicSharedMemorySize, SM2);
    cudaFuncSetAttribute(m6, cudaFuncAttributeMaxDynamicSharedMemorySize, SM2);
    cudaFuncSetAttribute(m7, cudaFuncAttributeMaxDynamicSharedMemorySize, SM7);

    // 0: weight pre-split (all 7 conv weights, chunked layout)
    presplit_w_kernel<<<(329728 + 255) / 256, 256>>>(w1, w2, w3, w4, w5, w6, w7);

    // 1-7: HMMA convs
    m1<<<dim3(64, 64), 256, SM1>>>(x,  wsp + W1H, wsp + W1L, b1, B1, 8192, 8192, 4092);
    m2<<<dim3(32, 64), 256, SM2>>>(B1, wsp + W2H, wsp + W2L, b2, B2, 4092, 4092, 2044);
    m2<<<dim3(16, 64), 256, SM2>>>(B2, wsp + W3H, wsp + W3L, b3, B3, 2044, 2044, 1020);
    m4<<<dim3(8, 64),  256, SM2>>>(B3, wsp + W4H, wsp + W4L, b4, B4, 1020, 1020, 508);
    m5<<<dim3(2, 64),  256, SM2>>>(B4, wsp + W5H, wsp + W5L, b5, B5, 254, 508, 125);
    m6<<<dim3(1, 64),  256, SM2>>>(B5, wsp + W6H, wsp + W6L, b6, B6, 62, 125, 29);
    m7<<<dim3(1, 64),  256, SM7>>>(B6, wsp + W7H, wsp + W7L, b7, B7, 29, 29, 14);

    // 8: masked max + MLP head
    head_kernel<<<64, 128>>>(B7, lenm, lw1, lb1, lw2, lb2, lw3, lb3,
                             (float*)d_out);
}